// round 3
// baseline (speedup 1.0000x reference)
#include <cuda_runtime.h>
#include <math.h>

// Problem dims
#define T_ 8
#define B_ 32
#define D_ 768
#define M_ 8
#define S_ 2
#define L_ 2
#define H_ 8
#define HD_ 96
#define d_ 384
#define P_ 16          // M_*S_
#define U_ 32          // P_*L_  (batched heb units, u = p*L + l)
#define KVROWS 256     // M_*B_
#define KVN 1536       // 2*D_

// ---------------- device state / scratch ----------------
__device__ float g_mem[M_*B_*D_];
__device__ float g_qall[(long)M_*T_*B_*D_];
__device__ float g_kv[(long)M_*KVROWS*KVN];
__device__ float g_o[M_*B_*D_];
__device__ float g_h[P_*B_*d_];
__device__ float g_pa[U_*B_*d_];
__device__ float g_pr[U_*B_*d_];
__device__ float g_dp[U_*B_*d_];
__device__ float g_sr[U_*B_*d_];
__device__ float g_gb[U_*B_*d_];
__device__ float g_W [(long)U_*d_*d_];
__device__ float g_Wr[(long)U_*d_*d_];
__device__ float g_t1[U_*B_*d_];
__device__ float g_nt[U_*B_*3*d_];
__device__ float g_mod[U_*B_*d_];
__device__ float g_asm[2*U_*B_*d_];
__device__ float g_C[(long)2*U_*d_*d_];
__device__ float g_sd[U_*d_];
__device__ float g_tmp[U_*B_*d_];
__device__ float g_outpre[M_*B_*D_];

// ---------------- f32x2 helpers ----------------
__device__ __forceinline__ unsigned long long pack2(float x, float y) {
    unsigned long long r;
    asm("mov.b64 %0, {%1, %2};" : "=l"(r) : "f"(x), "f"(y));
    return r;
}
__device__ __forceinline__ void fma2(unsigned long long& d, unsigned long long a, unsigned long long b) {
    asm("fma.rn.f32x2 %0, %1, %2, %0;" : "+l"(d) : "l"(a), "l"(b));
}
__device__ __forceinline__ float2 unpack2(unsigned long long v) {
    float2 f;
    asm("mov.b64 {%0, %1}, %2;" : "=f"(f.x), "=f"(f.y) : "l"(v));
    return f;
}

// ---------------- generic batched tiled GEMM (f32x2 packed, 4x8 microtile) ----
// C[z][i][j] = act( scale*(sum_k opA(A)[i][k]*opB(W)[k][j] + bias[z][j]) + add[z][i][j] )
// TRANSA: A stored [K, M] row stride lda. else [M, K] row stride lda.
// TRANSB: W row-major [N, K]. else W row-major [K, N].
// AMODE=1: A element (z,i,k) read from h-layout: A[((z*2 + k/384)*B_ + i)*384 + k%384]
// CMODE=1: C element (z,i,j) written to h-layout: C[((z*2 + j/384)*B_ + i)*384 + j%384]
// Tile BM=32, BN=128, BK=16; 128 threads; thread computes 4 rows x 8 cols.
// Requirements: M%32==0, N%128==0, K%16==0.
#define AS_STRIDE 36
#define BS_STRIDE 132
template<int AMODE, int CMODE, bool TRANSA, bool TRANSB>
__global__ __launch_bounds__(128) void gemm2_k(
                        const float* __restrict__ A, long aB, int lda,
                        const float* __restrict__ W, long wB, int zwrap,
                        const float* __restrict__ bias, long bB,
                        const float* __restrict__ add, long adB,
                        float* __restrict__ C, long cB,
                        int N, int K, float scale, int relu)
{
    __shared__ float As[16*AS_STRIDE];
    __shared__ float Bs[16*BS_STRIDE];
    const int tid = threadIdx.x;               // 128
    const int tx = tid & 15;                    // col group (8 cols)
    const int ty = tid >> 4;                    // row group (4 rows)
    const int z = blockIdx.z;
    const float* Ab = A + (long)z*aB;
    const float* Wb = W + (long)(zwrap ? (z % zwrap) : z)*wB;
    const int row0 = blockIdx.y*32, col0 = blockIdx.x*128;

    unsigned long long acc[4][4];
    #pragma unroll
    for (int r = 0; r < 4; r++)
        #pragma unroll
        for (int c = 0; c < 4; c++) acc[r][c] = 0ull;

    for (int k0 = 0; k0 < K; k0 += 16) {
        // A tile -> As[kk][row]
        if (TRANSA) {
            int kk = tid >> 3, r4 = (tid & 7)*4;
            float4 av = *(const float4*)&Ab[(long)(k0 + kk)*lda + row0 + r4];
            *(float4*)&As[kk*AS_STRIDE + r4] = av;
        } else {
            int r = tid >> 2, kc = (tid & 3)*4;
            float4 av;
            if (AMODE) {
                int k = k0 + kc; int sh = k / d_, kr = k % d_;
                av = *(const float4*)&Ab[(((long)z*2 + sh)*B_ + row0 + r)*d_ + kr];
            } else {
                av = *(const float4*)&Ab[(long)(row0 + r)*lda + k0 + kc];
            }
            As[(kc+0)*AS_STRIDE + r] = av.x;
            As[(kc+1)*AS_STRIDE + r] = av.y;
            As[(kc+2)*AS_STRIDE + r] = av.z;
            As[(kc+3)*AS_STRIDE + r] = av.w;
        }
        // B tile -> Bs[kk][j]   (16 x 128)
        #pragma unroll
        for (int it = 0; it < 4; it++) {
            int e = tid + it*128;
            if (TRANSB) {
                int j = e >> 2, kc = (e & 3)*4;
                float4 wv = *(const float4*)&Wb[(long)(col0 + j)*K + k0 + kc];
                Bs[(kc+0)*BS_STRIDE + j] = wv.x;
                Bs[(kc+1)*BS_STRIDE + j] = wv.y;
                Bs[(kc+2)*BS_STRIDE + j] = wv.z;
                Bs[(kc+3)*BS_STRIDE + j] = wv.w;
            } else {
                int kk = e >> 5, j4 = (e & 31)*4;
                float4 wv = *(const float4*)&Wb[(long)(k0 + kk)*N + col0 + j4];
                *(float4*)&Bs[kk*BS_STRIDE + j4] = wv;
            }
        }
        __syncthreads();
        #pragma unroll
        for (int kk = 0; kk < 16; kk++) {
            float4 a = *(const float4*)&As[kk*AS_STRIDE + ty*4];
            ulonglong2 bl = *(const ulonglong2*)&Bs[kk*BS_STRIDE + tx*8];
            ulonglong2 bh = *(const ulonglong2*)&Bs[kk*BS_STRIDE + tx*8 + 4];
            unsigned long long a0 = pack2(a.x, a.x);
            unsigned long long a1 = pack2(a.y, a.y);
            unsigned long long a2 = pack2(a.z, a.z);
            unsigned long long a3 = pack2(a.w, a.w);
            fma2(acc[0][0], a0, bl.x); fma2(acc[0][1], a0, bl.y); fma2(acc[0][2], a0, bh.x); fma2(acc[0][3], a0, bh.y);
            fma2(acc[1][0], a1, bl.x); fma2(acc[1][1], a1, bl.y); fma2(acc[1][2], a1, bh.x); fma2(acc[1][3], a1, bh.y);
            fma2(acc[2][0], a2, bl.x); fma2(acc[2][1], a2, bl.y); fma2(acc[2][2], a2, bh.x); fma2(acc[2][3], a2, bh.y);
            fma2(acc[3][0], a3, bl.x); fma2(acc[3][1], a3, bl.y); fma2(acc[3][2], a3, bh.x); fma2(acc[3][3], a3, bh.y);
        }
        __syncthreads();
    }

    float* Cb = C + (long)z*cB;
    const int colb = col0 + tx*8;
    #pragma unroll
    for (int r = 0; r < 4; r++) {
        int row = row0 + ty*4 + r;
        float v[8];
        #pragma unroll
        for (int c = 0; c < 4; c++) {
            float2 f = unpack2(acc[r][c]);
            v[c*2] = f.x; v[c*2+1] = f.y;
        }
        #pragma unroll
        for (int c = 0; c < 8; c++) {
            if (bias) v[c] += bias[(long)z*bB + colb + c];
            v[c] *= scale;
            if (add)  v[c] += add[(long)z*adB + (long)row*N + colb + c];
            if (relu) v[c] = fmaxf(v[c], 0.f);
        }
        if (CMODE) {
            int sh = colb / d_, jr = colb % d_;
            float* dst = C + (((long)z*2 + sh)*B_ + row)*d_ + jr;
            *(float4*)&dst[0] = make_float4(v[0], v[1], v[2], v[3]);
            *(float4*)&dst[4] = make_float4(v[4], v[5], v[6], v[7]);
        } else {
            float* dst = &Cb[(long)row*N + colb];
            *(float4*)&dst[0] = make_float4(v[0], v[1], v[2], v[3]);
            *(float4*)&dst[4] = make_float4(v[4], v[5], v[6], v[7]);
        }
    }
}

// ---------------- attention core (warp per (h,b,m)) ----------------
__global__ void attn2_k(int t)
{
    int gw = (blockIdx.x*blockDim.x + threadIdx.x) >> 5;
    int lane = threadIdx.x & 31;
    int h = gw & 7;
    int b = (gw >> 3) & 31;
    int m = gw >> 8;
    const float* qb = g_qall + ((long)m*T_*B_ + t*B_ + b)*D_ + h*HD_;
    float q0 = qb[lane], q1 = qb[lane + 32], q2 = qb[lane + 64];
    float a[M_];
    #pragma unroll
    for (int s = 0; s < M_; s++) {
        const float* kb = g_kv + ((long)m*KVROWS + s*B_ + b)*KVN + h*HD_;
        float p = q0*kb[lane] + q1*kb[lane + 32] + q2*kb[lane + 64];
        #pragma unroll
        for (int o = 16; o > 0; o >>= 1) p += __shfl_xor_sync(0xffffffffu, p, o);
        a[s] = p;
    }
    float mx = -1e30f;
    #pragma unroll
    for (int s = 0; s < M_; s++) mx = fmaxf(mx, a[s]);
    float sum = 0.f;
    #pragma unroll
    for (int s = 0; s < M_; s++) { a[s] = __expf(a[s] - mx); sum += a[s]; }
    float inv = 1.f / sum;
    float o0 = 0.f, o1 = 0.f, o2 = 0.f;
    #pragma unroll
    for (int s = 0; s < M_; s++) {
        const float* vb = g_kv + ((long)m*KVROWS + s*B_ + b)*KVN + D_ + h*HD_;
        float av = a[s]*inv;
        o0 += av*vb[lane]; o1 += av*vb[lane + 32]; o2 += av*vb[lane + 64];
    }
    float* ob = g_o + ((long)(m*B_ + b))*D_ + h*HD_;
    ob[lane] = o0; ob[lane + 32] = o1; ob[lane + 64] = o2;
}

// ---------------- plastic layer kernels (batched over U_ units) --------------
__global__ void gates_k(const float* __restrict__ alpha)
{
    int idx = blockIdx.x*256 + threadIdx.x;
    if (idx >= U_*B_*d_) return;
    int j = idx % d_; int b = (idx/d_) % B_; int u = idx/(B_*d_);
    const float* nt = g_nt + ((long)(u*B_ + b))*3*d_ + j*3;
    float pd = nt[0], ps = nt[1], pg = nt[2];
    float inv = 1.f / fmaxf(ps, 1e-6f);
    float dpv = tanhf(g_dp[idx] + pd*inv);
    float srv = 1.f/(1.f + __expf(-(g_sr[idx] + ps)));
    float gbv = 1.f/(1.f + __expf(-(g_gb[idx] + pg*inv)));
    g_dp[idx] = dpv; g_sr[idx] = srv; g_gb[idx] = gbv;
    g_mod[idx] = alpha[(long)u*d_ + j] * dpv * srv;
}

__global__ void sd_k(const float* __restrict__ decay)
{
    int u = blockIdx.x; int j = threadIdx.x; // 384 threads
    float s = 0.f;
    for (int b = 0; b < B_; b++) s += g_gb[((long)u*B_ + b)*d_ + j];
    s *= (1.f/B_);
    g_sd[u*d_ + j] = decay[(long)u*d_ + j] * (1.f/(1.f + __expf(-s)));
}

__global__ void rsm_k()   // row softmax of pa (which=0) / pr (which=1) over d_
{
    int row = blockIdx.x;      // 0..U_*B_-1
    int which = blockIdx.y;
    const float* src = (which ? g_pr : g_pa) + (long)row*d_;
    float* dst = g_asm + (long)which*U_*B_*d_ + (long)row*d_;
    int u = threadIdx.x;       // 128
    __shared__ float red[128];
    float v0 = src[u], v1 = src[u + 128], v2 = src[u + 256];
    float mx = fmaxf(v0, fmaxf(v1, v2));
    red[u] = mx; __syncthreads();
    #pragma unroll
    for (int o = 64; o > 0; o >>= 1) { if (u < o) red[u] = fmaxf(red[u], red[u + o]); __syncthreads(); }
    mx = red[0]; __syncthreads();
    float e0 = __expf(v0 - mx), e1 = __expf(v1 - mx), e2 = __expf(v2 - mx);
    red[u] = e0 + e1 + e2; __syncthreads();
    #pragma unroll
    for (int o = 64; o > 0; o >>= 1) { if (u < o) red[u] += red[u + o]; __syncthreads(); }
    float inv = 1.f / red[0];
    dst[u] = e0*inv; dst[u + 128] = e1*inv; dst[u + 256] = e2*inv;
}

// W_new[i][j] = W*(1-sd[i]) + rowsoftmax(W)[i][j]*C[i][j]
__global__ void wupd_k()
{
    int i = blockIdx.x, u = blockIdx.y, which = blockIdx.z;
    float* Wp = (which ? g_Wr : g_W) + ((long)u*d_ + i)*d_;
    const float* Cp = g_C + ((long)(which*U_ + u)*d_ + i)*d_;
    int t = threadIdx.x;  // 128
    __shared__ float red[128];
    float w0 = Wp[t], w1 = Wp[t + 128], w2 = Wp[t + 256];
    float mx = fmaxf(w0, fmaxf(w1, w2));
    red[t] = mx; __syncthreads();
    #pragma unroll
    for (int o = 64; o > 0; o >>= 1) { if (t < o) red[t] = fmaxf(red[t], red[t + o]); __syncthreads(); }
    mx = red[0]; __syncthreads();
    float e0 = __expf(w0 - mx), e1 = __expf(w1 - mx), e2 = __expf(w2 - mx);
    red[t] = e0 + e1 + e2; __syncthreads();
    #pragma unroll
    for (int o = 64; o > 0; o >>= 1) { if (t < o) red[t] += red[t + o]; __syncthreads(); }
    float invs = 1.f / red[0];
    float om = 1.f - g_sd[u*d_ + i];
    Wp[t]       = w0*om + e0*invs*Cp[t];
    Wp[t + 128] = w1*om + e1*invs*Cp[t + 128];
    Wp[t + 256] = w2*om + e2*invs*Cp[t + 256];
}

// ---------------- LayerNorm ----------------
__global__ void ln_k(const float* __restrict__ in,
                     float* __restrict__ out1, long o1Group,
                     float* __restrict__ out2,
                     const float* __restrict__ gam, const float* __restrict__ bet,
                     long gGroup, int N)
{
    int row = blockIdx.x;
    int u = threadIdx.x;   // 128
    int grp = row / B_, rb = row % B_;
    const float* x = in + (long)row*N;
    int nper = N / 128;    // 3 or 6
    float vals[6];
    float s = 0.f;
    for (int t = 0; t < nper; t++) { vals[t] = x[u + t*128]; s += vals[t]; }
    __shared__ float red[128];
    red[u] = s; __syncthreads();
    #pragma unroll
    for (int o = 64; o > 0; o >>= 1) { if (u < o) red[u] += red[u + o]; __syncthreads(); }
    float mu = red[0] / N; __syncthreads();
    float sq = 0.f;
    for (int t = 0; t < nper; t++) { float dv = vals[t] - mu; sq += dv*dv; }
    red[u] = sq; __syncthreads();
    #pragma unroll
    for (int o = 64; o > 0; o >>= 1) { if (u < o) red[u] += red[u + o]; __syncthreads(); }
    float rstd = rsqrtf(red[0] / N + 1e-5f);
    float* o1 = out1 + (long)grp*o1Group + (long)rb*N;
    const float* gp = gam + (long)grp*gGroup;
    const float* bp = bet + (long)grp*gGroup;
    for (int t = 0; t < nper; t++) {
        int j = u + t*128;
        float y = (vals[t] - mu)*rstd*gp[j] + bp[j];
        o1[j] = y;
        if (out2) out2[(long)row*N + j] = y;
    }
}

__global__ void clear_k()
{
    long idx = (long)blockIdx.x*256 + threadIdx.x;
    if (idx < (long)U_*B_*d_) {
        g_pa[idx] = 0.f; g_pr[idx] = 0.f; g_dp[idx] = 0.f; g_sr[idx] = 0.f; g_gb[idx] = 0.f;
    }
}

// ---------------- host launcher ----------------
extern "C" void kernel_launch(void* const* d_in, const int* in_sizes, int n_in,
                              void* d_out, int out_size)
{
    const float* x          = (const float*)d_in[0];
    const float* mem0       = (const float*)d_in[1];
    const float* attn_in_w  = (const float*)d_in[2];
    const float* attn_in_b  = (const float*)d_in[3];
    const float* attn_out_w = (const float*)d_in[4];
    const float* attn_out_b = (const float*)d_in[5];
    const float* heb_w      = (const float*)d_in[6];
    const float* heb_rw     = (const float*)d_in[7];
    const float* alpha      = (const float*)d_in[8];
    const float* decay      = (const float*)d_in[9];
    const float* ln_act_g   = (const float*)d_in[10];
    const float* ln_act_b   = (const float*)d_in[11];
    const float* ln_rec_g   = (const float*)d_in[12];
    const float* ln_rec_b   = (const float*)d_in[13];
    const float* pred_w1    = (const float*)d_in[14];
    const float* pred_b1    = (const float*)d_in[15];
    const float* pred_w2    = (const float*)d_in[16];
    const float* pred_b2    = (const float*)d_in[17];
    const float* out_w      = (const float*)d_in[18];
    const float* out_b      = (const float*)d_in[19];
    const float* ln_out_g   = (const float*)d_in[20];
    const float* ln_out_b   = (const float*)d_in[21];

    float *pmem, *pqall, *pkv, *po, *ph, *ppa, *ppr, *pt1, *pnt, *ptmp,
          *poutpre, *pW, *pWr, *pasm, *pmod, *pC;
    cudaGetSymbolAddress((void**)&pmem,    g_mem);
    cudaGetSymbolAddress((void**)&pqall,   g_qall);
    cudaGetSymbolAddress((void**)&pkv,     g_kv);
    cudaGetSymbolAddress((void**)&po,      g_o);
    cudaGetSymbolAddress((void**)&ph,      g_h);
    cudaGetSymbolAddress((void**)&ppa,     g_pa);
    cudaGetSymbolAddress((void**)&ppr,     g_pr);
    cudaGetSymbolAddress((void**)&pt1,     g_t1);
    cudaGetSymbolAddress((void**)&pnt,     g_nt);
    cudaGetSymbolAddress((void**)&ptmp,    g_tmp);
    cudaGetSymbolAddress((void**)&poutpre, g_outpre);
    cudaGetSymbolAddress((void**)&pW,      g_W);
    cudaGetSymbolAddress((void**)&pWr,     g_Wr);
    cudaGetSymbolAddress((void**)&pasm,    g_asm);
    cudaGetSymbolAddress((void**)&pmod,    g_mod);
    cudaGetSymbolAddress((void**)&pC,      g_C);

    const float qscale = 1.f / sqrtf((float)HD_);

    // init state
    cudaMemcpyAsync(pW,  heb_w,  sizeof(float)*(long)U_*d_*d_, cudaMemcpyDeviceToDevice, 0);
    cudaMemcpyAsync(pWr, heb_rw, sizeof(float)*(long)U_*d_*d_, cudaMemcpyDeviceToDevice, 0);
    cudaMemcpyAsync(pmem, mem0,  sizeof(float)*M_*B_*D_,       cudaMemcpyDeviceToDevice, 0);
    clear_k<<<(U_*B_*d_ + 255)/256, 256>>>();

    // q for all timesteps: per m, (T*B x 768) = x @ wq^T * qscale
    gemm2_k<0,0,false,true><<<dim3(6, 8, M_), 128>>>(x, 0, D_,
        attn_in_w, (long)3*D_*D_, 0, attn_in_b, (long)3*D_, nullptr, 0,
        pqall, (long)T_*B_*D_, D_, D_, qscale, 0);

    for (int t = 0; t < T_; t++) {
        // ---- Hebbian chain (batched over U_=32 units; uses only prev-step state)
        // t1 = relu(pa @ w1 + b1)
        gemm2_k<0,0,false,false><<<dim3(3, 1, U_), 128>>>(ppa, (long)B_*d_, d_,
            pred_w1, (long)d_*d_, 0, pred_b1, (long)d_, nullptr, 0,
            pt1, (long)B_*d_, d_, d_, 1.f, 1);
        // nt = t1 @ w2 + b2
        gemm2_k<0,0,false,false><<<dim3(9, 1, U_), 128>>>(pt1, (long)B_*d_, d_,
            pred_w2, (long)d_*3*d_, 0, pred_b2, (long)3*d_, nullptr, 0,
            pnt, (long)B_*3*d_, 3*d_, d_, 1.f, 0);
        gates_k<<<(U_*B_*d_ + 255)/256, 256>>>(alpha);
        sd_k<<<U_, d_>>>(decay);
        rsm_k<<<dim3(U_*B_, 2), 128>>>();
        // C[z] = (1/B) * asm[z]^T @ mod[z%U_]   z in [0, 2U)
        gemm2_k<0,0,true,false><<<dim3(3, 12, 2*U_), 128>>>(pasm, (long)B_*d_, d_,
            pmod, (long)B_*d_, U_, nullptr, 0, nullptr, 0,
            pC, (long)d_*d_, d_, B_, 1.f/B_, 0);
        wupd_k<<<dim3(d_, U_, 2), 128>>>();
        // rec_pre = pa @ Wr_new
        gemm2_k<0,0,false,false><<<dim3(3, 1, U_), 128>>>(ppa, (long)B_*d_, d_,
            pWr, (long)d_*d_, 0, nullptr, 0, nullptr, 0,
            ptmp, (long)B_*d_, d_, d_, 1.f, 0);
        // pr = LN(rec_pre)
        ln_k<<<U_*B_, 128>>>(ptmp, ppr, (long)B_*d_, nullptr,
            ln_rec_g, ln_rec_b, (long)d_, d_);

        // ---- attention chain
        // kv = mem @ [wk;wv]^T + b     [per m, 256 x 1536]
        gemm2_k<0,0,false,true><<<dim3(12, 8, M_), 128>>>(pmem, 0, D_,
            attn_in_w + (long)D_*D_, (long)3*D_*D_, 0, attn_in_b + D_, (long)3*D_, nullptr, 0,
            pkv, (long)KVROWS*KVN, KVN, D_, 1.f, 0);
        attn2_k<<<256, 256>>>(t);
        // h = scatter( o @ out_w^T + out_b )    (CMODE epilogue does a2h)
        gemm2_k<0,1,false,true><<<dim3(6, 1, M_), 128>>>(po, (long)B_*D_, D_,
            attn_out_w, (long)D_*D_, 0, attn_out_b, (long)D_, nullptr, 0,
            ph, 0, D_, D_, 1.f, 0);

        // ---- per-layer activation (serial over l; z = p in [0,16))
        for (int l = 0; l < L_; l++) {
            // act_pre = relu(h @ W_new + rec)
            gemm2_k<0,0,false,false><<<dim3(3, 1, P_), 128>>>(ph, (long)B_*d_, d_,
                pW + (long)l*d_*d_, (long)L_*d_*d_, 0, nullptr, 0,
                ppr + (long)l*B_*d_, (long)L_*B_*d_,
                ptmp, (long)B_*d_, d_, d_, 1.f, 1);
            // pa = LN(act_pre); h = same values
            ln_k<<<P_*B_, 128>>>(ptmp, ppa + (long)l*B_*d_, (long)L_*B_*d_, ph,
                ln_act_g + (long)l*d_, ln_act_b + (long)l*d_, (long)L_*d_, d_);
        }

        // ---- output projection (AMODE prologue does h2cat gather)
        gemm2_k<1,0,false,true><<<dim3(6, 1, M_), 128>>>(ph, 0, 0,
            out_w, (long)D_*D_, 0, out_b, (long)D_, nullptr, 0,
            poutpre, (long)B_*D_, D_, D_, 1.f, 0);
        // mem = LN(out)
        ln_k<<<M_*B_, 128>>>(poutpre, pmem, (long)B_*D_, nullptr,
            ln_out_g, ln_out_b, (long)D_, D_);
    }

    cudaMemcpyAsync(d_out, pmem, sizeof(float)*M_*B_*D_, cudaMemcpyDeviceToDevice, 0);
}

// round 4
// speedup vs baseline: 2.1624x; 2.1624x over previous
#include <cuda_runtime.h>
#include <math.h>

// Problem dims
#define T_ 8
#define B_ 32
#define D_ 768
#define M_ 8
#define S_ 2
#define L_ 2
#define H_ 8
#define HD_ 96
#define d_ 384
#define P_ 16          // M_*S_
#define U_ 32          // P_*L_
#define KVROWS 256     // M_*B_
#define KVN 1536       // 2*D_

// ---------------- device state / scratch ----------------
__device__ float g_mem[M_*B_*D_];
__device__ float g_qall[(long)M_*T_*B_*D_];
__device__ float g_kv[(long)M_*KVROWS*KVN];
__device__ float g_o[M_*B_*D_];
__device__ float g_h[P_*B_*d_];
__device__ float g_pa[U_*B_*d_];
__device__ float g_pr[U_*B_*d_];
__device__ float g_dp[U_*B_*d_];
__device__ float g_sr[U_*B_*d_];
__device__ float g_gb[U_*B_*d_];
__device__ float g_W [(long)U_*d_*d_];
__device__ float g_Wr[(long)U_*d_*d_];
__device__ float g_t1[U_*B_*d_];
__device__ float g_nt[U_*B_*3*d_];
__device__ float g_mod[U_*B_*d_];
__device__ float g_asm[2*U_*B_*d_];
__device__ float g_C[(long)2*U_*d_*d_];
__device__ float g_tmp[U_*B_*d_];
__device__ float g_outpre[M_*B_*D_];

// ---------------- f32x2 helpers ----------------
__device__ __forceinline__ unsigned long long pack2(float x, float y) {
    unsigned long long r;
    asm("mov.b64 %0, {%1, %2};" : "=l"(r) : "f"(x), "f"(y));
    return r;
}
__device__ __forceinline__ void fma2(unsigned long long& d, unsigned long long a, unsigned long long b) {
    asm("fma.rn.f32x2 %0, %1, %2, %0;" : "+l"(d) : "l"(a), "l"(b));
}
__device__ __forceinline__ float2 unpack2(unsigned long long v) {
    float2 f;
    asm("mov.b64 {%0, %1}, %2;" : "=f"(f.x), "=f"(f.y) : "l"(v));
    return f;
}

// ---------------- generic batched tiled GEMM (f32x2, R2-proven 4x4 tile) -----
// C[z][i][j] = act( scale*(sum_k opA(A)[i][k]*opB(W)[k][j] + bias[z][j]) + add[z][i][j] )
// TRANSA: A stored [K, M] row stride lda. else [M, K] row stride lda.
// TRANSB: W row-major [N, K]. else W row-major [K, N].
// AMODE=1: A element (z,i,k) read from h-layout: A[((z*2 + k/384)*B_ + i)*384 + k%384]
// CMODE=1: C element (z,i,j) written to h-layout: C[((z*2 + j/384)*B_ + i)*384 + j%384]
// zwrap!=0: weight batch index = z % zwrap.
// Tile BM=32, BN=64, BK=16; 128 threads; thread computes 4x4.
#define AS_STRIDE 36
#define BS_STRIDE 68
template<int AMODE, int CMODE, bool TRANSA, bool TRANSB>
__global__ __launch_bounds__(128) void gemm2_k(
                        const float* __restrict__ A, long aB, int lda,
                        const float* __restrict__ W, long wB, int zwrap,
                        const float* __restrict__ bias, long bB,
                        const float* __restrict__ add, long adB,
                        float* __restrict__ C, long cB,
                        int N, int K, float scale, int relu)
{
    __shared__ float As[16*AS_STRIDE];
    __shared__ float Bs[16*BS_STRIDE];
    const int tid = threadIdx.x;               // 128
    const int tx = tid & 15;                    // col group (4 cols)
    const int ty = tid >> 4;                    // row group (4 rows)
    const int z = blockIdx.z;
    const float* Ab = A + (long)z*aB;
    const float* Wb = W + (long)(zwrap ? (z % zwrap) : z)*wB;
    const int row0 = blockIdx.y*32, col0 = blockIdx.x*64;

    unsigned long long acc[4][2];
    #pragma unroll
    for (int r = 0; r < 4; r++) { acc[r][0] = 0ull; acc[r][1] = 0ull; }

    for (int k0 = 0; k0 < K; k0 += 16) {
        // A tile -> As[kk][row]
        if (TRANSA) {
            int kk = tid >> 3, r4 = (tid & 7)*4;
            float4 av = *(const float4*)&Ab[(long)(k0 + kk)*lda + row0 + r4];
            *(float4*)&As[kk*AS_STRIDE + r4] = av;
        } else {
            int r = tid >> 2, kc = (tid & 3)*4;
            float4 av;
            if (AMODE) {
                int k = k0 + kc; int sh = k / d_, kr = k % d_;
                av = *(const float4*)&A[(((long)z*2 + sh)*B_ + row0 + r)*d_ + kr];
            } else {
                av = *(const float4*)&Ab[(long)(row0 + r)*lda + k0 + kc];
            }
            As[(kc+0)*AS_STRIDE + r] = av.x;
            As[(kc+1)*AS_STRIDE + r] = av.y;
            As[(kc+2)*AS_STRIDE + r] = av.z;
            As[(kc+3)*AS_STRIDE + r] = av.w;
        }
        // B tile -> Bs[kk][j]   (16 x 64)
        #pragma unroll
        for (int it = 0; it < 2; it++) {
            int e = tid + it*128;
            if (TRANSB) {
                int j = e >> 2, kc = (e & 3)*4;
                float4 wv = *(const float4*)&Wb[(long)(col0 + j)*K + k0 + kc];
                Bs[(kc+0)*BS_STRIDE + j] = wv.x;
                Bs[(kc+1)*BS_STRIDE + j] = wv.y;
                Bs[(kc+2)*BS_STRIDE + j] = wv.z;
                Bs[(kc+3)*BS_STRIDE + j] = wv.w;
            } else {
                int kk = e >> 4, j4 = (e & 15)*4;
                float4 wv = *(const float4*)&Wb[(long)(k0 + kk)*N + col0 + j4];
                *(float4*)&Bs[kk*BS_STRIDE + j4] = wv;
            }
        }
        __syncthreads();
        #pragma unroll
        for (int kk = 0; kk < 16; kk++) {
            float4 a = *(const float4*)&As[kk*AS_STRIDE + ty*4];
            unsigned long long b0 = *(const unsigned long long*)&Bs[kk*BS_STRIDE + tx*4];
            unsigned long long b1 = *(const unsigned long long*)&Bs[kk*BS_STRIDE + tx*4 + 2];
            unsigned long long a0 = pack2(a.x, a.x);
            unsigned long long a1 = pack2(a.y, a.y);
            unsigned long long a2 = pack2(a.z, a.z);
            unsigned long long a3 = pack2(a.w, a.w);
            fma2(acc[0][0], a0, b0); fma2(acc[0][1], a0, b1);
            fma2(acc[1][0], a1, b0); fma2(acc[1][1], a1, b1);
            fma2(acc[2][0], a2, b0); fma2(acc[2][1], a2, b1);
            fma2(acc[3][0], a3, b0); fma2(acc[3][1], a3, b1);
        }
        __syncthreads();
    }

    float* Cb = C + (long)z*cB;
    const int colb = col0 + tx*4;
    #pragma unroll
    for (int r = 0; r < 4; r++) {
        int row = row0 + ty*4 + r;
        float2 v0 = unpack2(acc[r][0]);
        float2 v1 = unpack2(acc[r][1]);
        float v[4] = {v0.x, v0.y, v1.x, v1.y};
        #pragma unroll
        for (int c = 0; c < 4; c++) {
            if (bias) v[c] += bias[(long)z*bB + colb + c];
            v[c] *= scale;
            if (add)  v[c] += add[(long)z*adB + (long)row*N + colb + c];
            if (relu) v[c] = fmaxf(v[c], 0.f);
        }
        if (CMODE) {
            int sh = colb / d_, jr = colb % d_;
            float* dst = C + (((long)z*2 + sh)*B_ + row)*d_ + jr;
            *(float4*)dst = make_float4(v[0], v[1], v[2], v[3]);
        } else {
            *(float4*)&Cb[(long)row*N + colb] = make_float4(v[0], v[1], v[2], v[3]);
        }
    }
}

// ---------------- attention core (warp per (h,b,m)) ----------------
__global__ void attn2_k(int t)
{
    int gw = (blockIdx.x*blockDim.x + threadIdx.x) >> 5;
    int lane = threadIdx.x & 31;
    int h = gw & 7;
    int b = (gw >> 3) & 31;
    int m = gw >> 8;
    const float* qb = g_qall + ((long)m*T_*B_ + t*B_ + b)*D_ + h*HD_;
    float q0 = qb[lane], q1 = qb[lane + 32], q2 = qb[lane + 64];
    float a[M_];
    #pragma unroll
    for (int s = 0; s < M_; s++) {
        const float* kb = g_kv + ((long)m*KVROWS + s*B_ + b)*KVN + h*HD_;
        float p = q0*kb[lane] + q1*kb[lane + 32] + q2*kb[lane + 64];
        #pragma unroll
        for (int o = 16; o > 0; o >>= 1) p += __shfl_xor_sync(0xffffffffu, p, o);
        a[s] = p;
    }
    float mx = -1e30f;
    #pragma unroll
    for (int s = 0; s < M_; s++) mx = fmaxf(mx, a[s]);
    float sum = 0.f;
    #pragma unroll
    for (int s = 0; s < M_; s++) { a[s] = __expf(a[s] - mx); sum += a[s]; }
    float inv = 1.f / sum;
    float o0 = 0.f, o1 = 0.f, o2 = 0.f;
    #pragma unroll
    for (int s = 0; s < M_; s++) {
        const float* vb = g_kv + ((long)m*KVROWS + s*B_ + b)*KVN + D_ + h*HD_;
        float av = a[s]*inv;
        o0 += av*vb[lane]; o1 += av*vb[lane + 32]; o2 += av*vb[lane + 64];
    }
    float* ob = g_o + ((long)(m*B_ + b))*D_ + h*HD_;
    ob[lane] = o0; ob[lane + 32] = o1; ob[lane + 64] = o2;
}

// ---------------- plastic layer kernels (batched over U_ units) --------------
__global__ void gates_k(const float* __restrict__ alpha)
{
    int idx = blockIdx.x*256 + threadIdx.x;
    if (idx >= U_*B_*d_) return;
    int j = idx % d_; int b = (idx/d_) % B_; int u = idx/(B_*d_);
    const float* nt = g_nt + ((long)(u*B_ + b))*3*d_ + j*3;
    float pd = nt[0], ps = nt[1], pg = nt[2];
    float inv = 1.f / fmaxf(ps, 1e-6f);
    float dpv = tanhf(g_dp[idx] + pd*inv);
    float srv = 1.f/(1.f + __expf(-(g_sr[idx] + ps)));
    float gbv = 1.f/(1.f + __expf(-(g_gb[idx] + pg*inv)));
    g_dp[idx] = dpv; g_sr[idx] = srv; g_gb[idx] = gbv;
    g_mod[idx] = alpha[(long)u*d_ + j] * dpv * srv;
}

__global__ void rsm_k()   // row softmax of pa (which=0) / pr (which=1) over d_
{
    int row = blockIdx.x;      // 0..U_*B_-1
    int which = blockIdx.y;
    const float* src = (which ? g_pr : g_pa) + (long)row*d_;
    float* dst = g_asm + (long)which*U_*B_*d_ + (long)row*d_;
    int u = threadIdx.x;       // 128
    __shared__ float red[128];
    float v0 = src[u], v1 = src[u + 128], v2 = src[u + 256];
    float mx = fmaxf(v0, fmaxf(v1, v2));
    red[u] = mx; __syncthreads();
    #pragma unroll
    for (int o = 64; o > 0; o >>= 1) { if (u < o) red[u] = fmaxf(red[u], red[u + o]); __syncthreads(); }
    mx = red[0]; __syncthreads();
    float e0 = __expf(v0 - mx), e1 = __expf(v1 - mx), e2 = __expf(v2 - mx);
    red[u] = e0 + e1 + e2; __syncthreads();
    #pragma unroll
    for (int o = 64; o > 0; o >>= 1) { if (u < o) red[u] += red[u + o]; __syncthreads(); }
    float inv = 1.f / red[0];
    dst[u] = e0*inv; dst[u + 128] = e1*inv; dst[u + 256] = e2*inv;
}

// W_new[i][j] = W*(1-sd[i]) + rowsoftmax(W)[i][j]*C[i][j]   (sd computed in-block)
__global__ void wupd_k(const float* __restrict__ decay)
{
    int i = blockIdx.x, u = blockIdx.y, which = blockIdx.z;
    float* Wp = (which ? g_Wr : g_W) + ((long)u*d_ + i)*d_;
    const float* Cp = g_C + ((long)(which*U_ + u)*d_ + i)*d_;
    int t = threadIdx.x;  // 128
    __shared__ float red[128];
    __shared__ float sdsh;
    if (t < 32) {
        float v = g_gb[((long)u*B_ + t)*d_ + i];
        #pragma unroll
        for (int o = 16; o > 0; o >>= 1) v += __shfl_xor_sync(0xffffffffu, v, o);
        if (t == 0) {
            float s = v*(1.f/B_);
            sdsh = decay[(long)u*d_ + i] * (1.f/(1.f + __expf(-s)));
        }
    }
    float w0 = Wp[t], w1 = Wp[t + 128], w2 = Wp[t + 256];
    float mx = fmaxf(w0, fmaxf(w1, w2));
    red[t] = mx; __syncthreads();
    #pragma unroll
    for (int o = 64; o > 0; o >>= 1) { if (t < o) red[t] = fmaxf(red[t], red[t + o]); __syncthreads(); }
    mx = red[0]; __syncthreads();
    float e0 = __expf(w0 - mx), e1 = __expf(w1 - mx), e2 = __expf(w2 - mx);
    red[t] = e0 + e1 + e2; __syncthreads();
    #pragma unroll
    for (int o = 64; o > 0; o >>= 1) { if (t < o) red[t] += red[t + o]; __syncthreads(); }
    float invs = 1.f / red[0];
    float om = 1.f - sdsh;
    Wp[t]       = w0*om + e0*invs*Cp[t];
    Wp[t + 128] = w1*om + e1*invs*Cp[t + 128];
    Wp[t + 256] = w2*om + e2*invs*Cp[t + 256];
}

// ---------------- LayerNorm ----------------
__global__ void ln_k(const float* __restrict__ in,
                     float* __restrict__ out1, long o1Group,
                     float* __restrict__ out2,
                     const float* __restrict__ gam, const float* __restrict__ bet,
                     long gGroup, int N)
{
    int row = blockIdx.x;
    int u = threadIdx.x;   // 128
    int grp = row / B_, rb = row % B_;
    const float* x = in + (long)row*N;
    int nper = N / 128;    // 3 or 6
    float vals[6];
    float s = 0.f;
    for (int t = 0; t < nper; t++) { vals[t] = x[u + t*128]; s += vals[t]; }
    __shared__ float red[128];
    red[u] = s; __syncthreads();
    #pragma unroll
    for (int o = 64; o > 0; o >>= 1) { if (u < o) red[u] += red[u + o]; __syncthreads(); }
    float mu = red[0] / N; __syncthreads();
    float sq = 0.f;
    for (int t = 0; t < nper; t++) { float dv = vals[t] - mu; sq += dv*dv; }
    red[u] = sq; __syncthreads();
    #pragma unroll
    for (int o = 64; o > 0; o >>= 1) { if (u < o) red[u] += red[u + o]; __syncthreads(); }
    float rstd = rsqrtf(red[0] / N + 1e-5f);
    float* o1 = out1 + (long)grp*o1Group + (long)rb*N;
    const float* gp = gam + (long)grp*gGroup;
    const float* bp = bet + (long)grp*gGroup;
    for (int t = 0; t < nper; t++) {
        int j = u + t*128;
        float y = (vals[t] - mu)*rstd*gp[j] + bp[j];
        o1[j] = y;
        if (out2) out2[(long)row*N + j] = y;
    }
}

__global__ void clear_k()
{
    long idx = (long)blockIdx.x*256 + threadIdx.x;
    if (idx < (long)U_*B_*d_) {
        g_pa[idx] = 0.f; g_pr[idx] = 0.f; g_dp[idx] = 0.f; g_sr[idx] = 0.f; g_gb[idx] = 0.f;
    }
}

// ---------------- host launcher ----------------
extern "C" void kernel_launch(void* const* d_in, const int* in_sizes, int n_in,
                              void* d_out, int out_size)
{
    const float* x          = (const float*)d_in[0];
    const float* mem0       = (const float*)d_in[1];
    const float* attn_in_w  = (const float*)d_in[2];
    const float* attn_in_b  = (const float*)d_in[3];
    const float* attn_out_w = (const float*)d_in[4];
    const float* attn_out_b = (const float*)d_in[5];
    const float* heb_w      = (const float*)d_in[6];
    const float* heb_rw     = (const float*)d_in[7];
    const float* alpha      = (const float*)d_in[8];
    const float* decay      = (const float*)d_in[9];
    const float* ln_act_g   = (const float*)d_in[10];
    const float* ln_act_b   = (const float*)d_in[11];
    const float* ln_rec_g   = (const float*)d_in[12];
    const float* ln_rec_b   = (const float*)d_in[13];
    const float* pred_w1    = (const float*)d_in[14];
    const float* pred_b1    = (const float*)d_in[15];
    const float* pred_w2    = (const float*)d_in[16];
    const float* pred_b2    = (const float*)d_in[17];
    const float* out_w      = (const float*)d_in[18];
    const float* out_b      = (const float*)d_in[19];
    const float* ln_out_g   = (const float*)d_in[20];
    const float* ln_out_b   = (const float*)d_in[21];

    float *pmem, *pqall, *pkv, *po, *ph, *ppa, *ppr, *pt1, *pnt, *ptmp,
          *poutpre, *pW, *pWr, *pasm, *pmod, *pC;
    cudaGetSymbolAddress((void**)&pmem,    g_mem);
    cudaGetSymbolAddress((void**)&pqall,   g_qall);
    cudaGetSymbolAddress((void**)&pkv,     g_kv);
    cudaGetSymbolAddress((void**)&po,      g_o);
    cudaGetSymbolAddress((void**)&ph,      g_h);
    cudaGetSymbolAddress((void**)&ppa,     g_pa);
    cudaGetSymbolAddress((void**)&ppr,     g_pr);
    cudaGetSymbolAddress((void**)&pt1,     g_t1);
    cudaGetSymbolAddress((void**)&pnt,     g_nt);
    cudaGetSymbolAddress((void**)&ptmp,    g_tmp);
    cudaGetSymbolAddress((void**)&poutpre, g_outpre);
    cudaGetSymbolAddress((void**)&pW,      g_W);
    cudaGetSymbolAddress((void**)&pWr,     g_Wr);
    cudaGetSymbolAddress((void**)&pasm,    g_asm);
    cudaGetSymbolAddress((void**)&pmod,    g_mod);
    cudaGetSymbolAddress((void**)&pC,      g_C);

    const float qscale = 1.f / sqrtf((float)HD_);

    // init state
    cudaMemcpyAsync(pW,  heb_w,  sizeof(float)*(long)U_*d_*d_, cudaMemcpyDeviceToDevice, 0);
    cudaMemcpyAsync(pWr, heb_rw, sizeof(float)*(long)U_*d_*d_, cudaMemcpyDeviceToDevice, 0);
    cudaMemcpyAsync(pmem, mem0,  sizeof(float)*M_*B_*D_,       cudaMemcpyDeviceToDevice, 0);
    clear_k<<<(U_*B_*d_ + 255)/256, 256>>>();

    // q for all timesteps: per m, (T*B x 768) = x @ wq^T * qscale
    gemm2_k<0,0,false,true><<<dim3(12, 8, M_), 128>>>(x, 0, D_,
        attn_in_w, (long)3*D_*D_, 0, attn_in_b, (long)3*D_, nullptr, 0,
        pqall, (long)T_*B_*D_, D_, D_, qscale, 0);

    for (int t = 0; t < T_; t++) {
        // ---- Hebbian chain (batched over U_=32 units; uses only prev-step state)
        gemm2_k<0,0,false,false><<<dim3(6, 1, U_), 128>>>(ppa, (long)B_*d_, d_,
            pred_w1, (long)d_*d_, 0, pred_b1, (long)d_, nullptr, 0,
            pt1, (long)B_*d_, d_, d_, 1.f, 1);
        gemm2_k<0,0,false,false><<<dim3(18, 1, U_), 128>>>(pt1, (long)B_*d_, d_,
            pred_w2, (long)d_*3*d_, 0, pred_b2, (long)3*d_, nullptr, 0,
            pnt, (long)B_*3*d_, 3*d_, d_, 1.f, 0);
        gates_k<<<(U_*B_*d_ + 255)/256, 256>>>(alpha);
        rsm_k<<<dim3(U_*B_, 2), 128>>>();
        // C[z] = (1/B) * asm[z]^T @ mod[z%U_]   z in [0, 2U)
        gemm2_k<0,0,true,false><<<dim3(6, 12, 2*U_), 128>>>(pasm, (long)B_*d_, d_,
            pmod, (long)B_*d_, U_, nullptr, 0, nullptr, 0,
            pC, (long)d_*d_, d_, B_, 1.f/B_, 0);
        wupd_k<<<dim3(d_, U_, 2), 128>>>(decay);
        // rec_pre = pa @ Wr_new ; pr = LN(rec_pre)
        gemm2_k<0,0,false,false><<<dim3(6, 1, U_), 128>>>(ppa, (long)B_*d_, d_,
            pWr, (long)d_*d_, 0, nullptr, 0, nullptr, 0,
            ptmp, (long)B_*d_, d_, d_, 1.f, 0);
        ln_k<<<U_*B_, 128>>>(ptmp, ppr, (long)B_*d_, nullptr,
            ln_rec_g, ln_rec_b, (long)d_, d_);

        // ---- attention chain
        gemm2_k<0,0,false,true><<<dim3(24, 8, M_), 128>>>(pmem, 0, D_,
            attn_in_w + (long)D_*D_, (long)3*D_*D_, 0, attn_in_b + D_, (long)3*D_, nullptr, 0,
            pkv, (long)KVROWS*KVN, KVN, D_, 1.f, 0);
        attn2_k<<<256, 256>>>(t);
        // h = scatter( o @ out_w^T + out_b )   (CMODE epilogue does a2h)
        gemm2_k<0,1,false,true><<<dim3(12, 1, M_), 128>>>(po, (long)B_*D_, D_,
            attn_out_w, (long)D_*D_, 0, attn_out_b, (long)D_, nullptr, 0,
            ph, 0, D_, D_, 1.f, 0);

        // ---- per-layer activation (serial over l; z = p in [0,16))
        for (int l = 0; l < L_; l++) {
            gemm2_k<0,0,false,false><<<dim3(6, 1, P_), 128>>>(ph, (long)B_*d_, d_,
                pW + (long)l*d_*d_, (long)L_*d_*d_, 0, nullptr, 0,
                ppr + (long)l*B_*d_, (long)L_*B_*d_,
                ptmp, (long)B_*d_, d_, d_, 1.f, 1);
            ln_k<<<P_*B_, 128>>>(ptmp, ppa + (long)l*B_*d_, (long)L_*B_*d_, ph,
                ln_act_g + (long)l*d_, ln_act_b + (long)l*d_, (long)L_*d_, d_);
        }

        // ---- output projection (AMODE prologue does h2cat gather)
        gemm2_k<1,0,false,true><<<dim3(12, 1, M_), 128>>>(ph, 0, 0,
            out_w, (long)D_*D_, 0, out_b, (long)D_, nullptr, 0,
            poutpre, (long)B_*D_, D_, D_, 1.f, 0);
        ln_k<<<M_*B_, 128>>>(poutpre, pmem, (long)B_*D_, nullptr,
            ln_out_g, ln_out_b, (long)D_, D_);
    }

    cudaMemcpyAsync(d_out, pmem, sizeof(float)*M_*B_*D_, cudaMemcpyDeviceToDevice, 0);
}